// round 15
// baseline (speedup 1.0000x reference)
#include <cuda_runtime.h>
#include <cuda_fp16.h>
#include <cstdint>

static constexpr int Bn = 2;
static constexpr int Ln = 2048;
static constexpr int Dn = 1536;
static constexpr int NPAIR = 272;                      // sum_{j<16}(2j+2)
static constexpr int BK = 64;                          // k per stage
static constexpr int NSTG = Dn / BK;                   // 24
static constexpr int NK16 = Dn / 16;                   // 96
static constexpr int A_TILE_B = 64 * BK * 2;           // 8192
static constexpr int B_TILE_B = 128 * BK * 2;          // 16384
static constexpr int STAGE_B = A_TILE_B + B_TILE_B;    // 24576
static constexpr int NSTAGE = 4;
static constexpr int WTAB_OFF = NSTAGE * STAGE_B;      // 98304
static constexpr int WTAB_B = 2 * NK16 * 4 * 2 * 4;    // 6144
static constexpr int SMEM_DYN = WTAB_OFF + WTAB_B;     // 104448 -> 2 CTAs/SM

// single f16 plane per batch: g_h16[b][row][d] = rn16(H)
__device__ __align__(16) __half g_h16[2ull * Ln * Dn];

// ---------------------------------------------------------------- convert
__global__ __launch_bounds__(256) void cvt_kernel(const float* __restrict__ H)
{
    const int idx = blockIdx.x * 256 + threadIdx.x;   // Bn*Ln*(Dn/4)
    const int d4  = idx % (Dn / 4);
    const int rb  = idx / (Dn / 4);                   // b*Ln + row
    const int d0  = d4 * 4;

    const float4 h = *reinterpret_cast<const float4*>(H + (size_t)rb * Dn + d0);
    __half2* q = reinterpret_cast<__half2*>(g_h16 + (size_t)rb * Dn + d0);
    q[0] = __floats2half2_rn(h.x, h.y);
    q[1] = __floats2half2_rn(h.z, h.w);
}

// ---------------------------------------------------------------- helpers
__device__ __forceinline__ uint32_t s2u(const void* p) {
    uint32_t a;
    asm("{ .reg .u64 t; cvta.to.shared.u64 t, %1; cvt.u32.u64 %0, t; }" : "=r"(a) : "l"(p));
    return a;
}

// swizzled byte offset inside a (rows x 64 f16) tile (128B rows)
__device__ __forceinline__ uint32_t swz(int row, int c) {
    return (uint32_t)(row * 128 + ((c ^ (row & 7)) << 4));
}

__device__ __forceinline__ uint32_t h2mul(uint32_t a, uint32_t b) {
    __half2 r = __hmul2(*reinterpret_cast<__half2*>(&a), *reinterpret_cast<__half2*>(&b));
    return *reinterpret_cast<uint32_t*>(&r);
}

#define LDSM4(R0, R1, R2, R3, addr)                                            \
    asm volatile("ldmatrix.sync.aligned.m8n8.x4.shared.b16 {%0,%1,%2,%3}, [%4];" \
                 : "=r"(R0), "=r"(R1), "=r"(R2), "=r"(R3) : "r"(addr))

#define MMA(C, A, B)                                                              \
    asm volatile(                                                                 \
        "mma.sync.aligned.m16n8k16.row.col.f32.f16.f16.f32 "                      \
        "{%0,%1,%2,%3},{%4,%5,%6,%7},{%8,%9},{%0,%1,%2,%3};"                      \
        : "+f"((C)[0]), "+f"((C)[1]), "+f"((C)[2]), "+f"((C)[3])                  \
        : "r"((A)[0]), "r"((A)[1]), "r"((A)[2]), "r"((A)[3]),                     \
          "r"((B)[0]), "r"((B)[1]))

// ---------------------------------------------------------------- gram GEMM
// 128 threads = 4 warps in 2(m)x2(n); warp tile 32x64 PER t; CTA tile 64x128
// Flat loop over 96 global k16 steps; next-step fragments (possibly from the
// NEXT stage's buffer, already resident with the 4-deep ring) prefetch during
// current step's MMAs, so stage barriers expose no LDSM preamble.
__global__ __launch_bounds__(128, 2)
void gram_hmma(const float* __restrict__ W, const float* __restrict__ bias,
               float* __restrict__ out)
{
    extern __shared__ __align__(1024) char smem_raw[];
    const uint32_t sb = s2u(smem_raw);

    const int tid = threadIdx.x;
    const int wid = tid >> 5;
    const int lane = tid & 31;

    const int wm = (wid >> 1) * 32;   // 0,32
    const int wn = (wid & 1) * 64;    // 0,64

    const int a_row = lane & 15;
    const int ak3   = lane >> 4;
    const int b_row = (lane & 7) + (lane >> 4) * 8;
    const int bk3   = (lane >> 3) & 1;
    const int cquad = lane & 3;

    // decode (row-tile i of 64, col-tile j of 128), i in [0, 2j+1]
    int rem = blockIdx.x, j = 0;
    while (rem >= 2 * j + 2) { rem -= 2 * j + 2; ++j; }
    const int i = rem;
    const int b = blockIdx.y;
    const int gi0 = i * 64, gj0 = j * 128;
    const bool mirror = (i < 2 * j);

    const __half* srcA = g_h16 + ((size_t)b * Ln + gi0) * Dn;   // 64 rows
    const __half* srcB = g_h16 + ((size_t)b * Ln + gj0) * Dn;   // 128 rows

    auto load_stage = [&](int s, int buf) {
        const int k0 = s * BK;
        const uint32_t sbase = sb + buf * STAGE_B;
        {
            const __half* base = srcA + k0;
#pragma unroll
            for (int q = 0; q < 4; ++q) {
                const int chunk = tid + 128 * q;
                const int row = chunk >> 3, c = chunk & 7;
                asm volatile("cp.async.cg.shared.global [%0], [%1], 16;"
                             :: "r"(sbase + swz(row, c)),
                                "l"(base + (size_t)row * Dn + c * 8) : "memory");
            }
        }
        {
            const __half* base = srcB + k0;
            const uint32_t tb = sbase + A_TILE_B;
#pragma unroll
            for (int q = 0; q < 8; ++q) {
                const int chunk = tid + 128 * q;
                const int row = chunk >> 3, c = chunk & 7;
                asm volatile("cp.async.cg.shared.global [%0], [%1], 16;"
                             :: "r"(tb + swz(row, c)),
                                "l"(base + (size_t)row * Dn + c * 8) : "memory");
            }
        }
        asm volatile("cp.async.commit_group;" ::: "memory");
    };

    load_stage(0, 0);
    load_stage(1, 1);
    load_stage(2, 2);

    // w table: [t][k16][c][e] -> __half2 (w[k], w[k+1]), k = k16*16 + e*8 + c*2
    for (int it = 0; it < 12; ++it) {
        const int idx = tid + 128 * it;          // 0..1535
        const int t = idx / 768;
        const int r = idx % 768;
        const int k16 = r >> 3;
        const int c = (r >> 1) & 3;
        const int e = r & 1;
        const int k = k16 * 16 + e * 8 + c * 2;
        const float* wr = W + (size_t)t * (2 * Dn);
        __half2 v = __floats2half2_rn(wr[k], wr[k + 1]);
        asm volatile("st.shared.u32 [%0], %1;"
                     :: "r"(sb + WTAB_OFF + idx * 4),
                        "r"(*reinterpret_cast<uint32_t*>(&v)) : "memory");
    }

    float acc[2][2][8][4];
#pragma unroll
    for (int t = 0; t < 2; ++t)
#pragma unroll
        for (int mt = 0; mt < 2; ++mt)
#pragma unroll
            for (int nt = 0; nt < 8; ++nt)
#pragma unroll
                for (int e = 0; e < 4; ++e) acc[t][mt][nt][e] = 0.f;

    auto waddr = [&](int t, int k16) {
        return sb + WTAB_OFF + (((t * NK16 + k16) * 4 + cquad) * 2) * 4;
    };
    // smem base of the tile pair holding global k16 step g
    auto At_of = [&](int g) { return sb + ((g >> 2) & 3) * STAGE_B; };

    // persistent fragment state
    uint32_t bh[2][8][2], araw[2][4], w0[2][2], w1[2][2];

#pragma unroll 1
    for (int g = 0; g < NK16; ++g) {
        const int s16 = g & 3;
        if (s16 == 0) {
            const int s = g >> 2;
            const int slack = NSTG - 2 - s;
            if (slack >= 2)
                asm volatile("cp.async.wait_group 2;" ::: "memory");
            else if (slack == 1)
                asm volatile("cp.async.wait_group 1;" ::: "memory");
            else
                asm volatile("cp.async.wait_group 0;" ::: "memory");
            __syncthreads();
            if (s + 3 < NSTG) load_stage(s + 3, (s + 3) & 3);

            if (g == 0) {
                // one-time preamble for step 0
                const uint32_t At = At_of(0), Bt = At + A_TILE_B;
#pragma unroll
                for (int n2 = 0; n2 < 4; ++n2) {
                    const int rB = wn + n2 * 16 + b_row;
                    LDSM4(bh[0][n2 * 2][0], bh[0][n2 * 2][1],
                          bh[0][n2 * 2 + 1][0], bh[0][n2 * 2 + 1][1], Bt + swz(rB, bk3));
                }
#pragma unroll
                for (int mt = 0; mt < 2; ++mt) {
                    const int rA = wm + mt * 16 + a_row;
                    LDSM4(araw[mt][0], araw[mt][1], araw[mt][2], araw[mt][3],
                          At + swz(rA, ak3));
                }
                asm volatile("ld.shared.v2.u32 {%0,%1}, [%2];"
                             : "=r"(w0[0][0]), "=r"(w0[0][1]) : "r"(waddr(0, 0)));
                asm volatile("ld.shared.v2.u32 {%0,%1}, [%2];"
                             : "=r"(w1[0][0]), "=r"(w1[0][1]) : "r"(waddr(1, 0)));
            }
        }

        const int cur = g & 1;
        const bool has_next = (g + 1 < NK16);

        // prefetch next step's B fragments + w pairs (next buffer if stage crosses)
        if (has_next) {
            const int gn = g + 1;
            const uint32_t Bt_n = At_of(gn) + A_TILE_B;
            const int cbn = (gn & 3) * 2 + bk3;
#pragma unroll
            for (int n2 = 0; n2 < 4; ++n2) {
                const int rB = wn + n2 * 16 + b_row;
                LDSM4(bh[cur ^ 1][n2 * 2][0], bh[cur ^ 1][n2 * 2][1],
                      bh[cur ^ 1][n2 * 2 + 1][0], bh[cur ^ 1][n2 * 2 + 1][1],
                      Bt_n + swz(rB, cbn));
            }
            asm volatile("ld.shared.v2.u32 {%0,%1}, [%2];"
                         : "=r"(w0[cur ^ 1][0]), "=r"(w0[cur ^ 1][1])
                         : "r"(waddr(0, gn)));
            asm volatile("ld.shared.v2.u32 {%0,%1}, [%2];"
                         : "=r"(w1[cur ^ 1][0]), "=r"(w1[cur ^ 1][1])
                         : "r"(waddr(1, gn)));
        }

        // a0 = araw .* w0
        uint32_t a0[2][4];
#pragma unroll
        for (int mt = 0; mt < 2; ++mt) {
            a0[mt][0] = h2mul(araw[mt][0], w0[cur][0]);
            a0[mt][1] = h2mul(araw[mt][1], w0[cur][0]);
            a0[mt][2] = h2mul(araw[mt][2], w0[cur][1]);
            a0[mt][3] = h2mul(araw[mt][3], w0[cur][1]);
        }
#pragma unroll
        for (int nt = 0; nt < 8; ++nt)
#pragma unroll
            for (int mt = 0; mt < 2; ++mt)
                MMA(acc[0][mt][nt], a0[mt], bh[cur][nt]);

        // a1 = araw .* w1; araw then dead -> reload for next step
        uint32_t a1[2][4];
#pragma unroll
        for (int mt = 0; mt < 2; ++mt) {
            a1[mt][0] = h2mul(araw[mt][0], w1[cur][0]);
            a1[mt][1] = h2mul(araw[mt][1], w1[cur][0]);
            a1[mt][2] = h2mul(araw[mt][2], w1[cur][1]);
            a1[mt][3] = h2mul(araw[mt][3], w1[cur][1]);
        }
        if (has_next) {
            const int gn = g + 1;
            const uint32_t At_n = At_of(gn);
            const int can = (gn & 3) * 2 + ak3;
#pragma unroll
            for (int mt = 0; mt < 2; ++mt) {
                const int rA = wm + mt * 16 + a_row;
                LDSM4(araw[mt][0], araw[mt][1], araw[mt][2], araw[mt][3],
                      At_n + swz(rA, can));
            }
        }
#pragma unroll
        for (int nt = 0; nt < 8; ++nt)
#pragma unroll
            for (int mt = 0; mt < 2; ++mt)
                MMA(acc[1][mt][nt], a1[mt], bh[cur][nt]);
    }

    // ------------------------------------------------------------ epilogue
    const float b0 = __ldg(&bias[0]);
    const float b1 = __ldg(&bias[1]);
    float2* o2 = reinterpret_cast<float2*>(out) + (size_t)b * Ln * Ln;
    const int r4 = lane >> 2;
    const int c4 = (lane & 3) * 2;

#pragma unroll
    for (int mt = 0; mt < 2; ++mt) {
#pragma unroll
        for (int nt = 0; nt < 8; ++nt) {
            const int i0 = gi0 + wm + mt * 16 + r4;
            const int j0 = gj0 + wn + nt * 8 + c4;
            const float2 p00 = make_float2(acc[0][mt][nt][0] + b0, acc[1][mt][nt][0] + b1);
            const float2 p01 = make_float2(acc[0][mt][nt][1] + b0, acc[1][mt][nt][1] + b1);
            const float2 p10 = make_float2(acc[0][mt][nt][2] + b0, acc[1][mt][nt][2] + b1);
            const float2 p11 = make_float2(acc[0][mt][nt][3] + b0, acc[1][mt][nt][3] + b1);
            o2[(size_t)i0 * Ln + j0]           = p00;
            o2[(size_t)i0 * Ln + j0 + 1]       = p01;
            o2[(size_t)(i0 + 8) * Ln + j0]     = p10;
            o2[(size_t)(i0 + 8) * Ln + j0 + 1] = p11;
            if (mirror) {
                o2[(size_t)j0 * Ln + i0]           = p00;
                o2[(size_t)(j0 + 1) * Ln + i0]     = p01;
                o2[(size_t)j0 * Ln + i0 + 8]       = p10;
                o2[(size_t)(j0 + 1) * Ln + i0 + 8] = p11;
            }
        }
    }
}

// ---------------------------------------------------------------- launch
extern "C" void kernel_launch(void* const* d_in, const int* in_sizes, int n_in,
                              void* d_out, int out_size)
{
    const float* H    = (const float*)d_in[0];
    const float* W    = (const float*)d_in[1];
    const float* bias = (const float*)d_in[2];
    float* out = (float*)d_out;

    cudaFuncSetAttribute(gram_hmma, cudaFuncAttributeMaxDynamicSharedMemorySize, SMEM_DYN);

    cvt_kernel<<<(Bn * Ln * (Dn / 4)) / 256, 256>>>(H);

    dim3 grid(NPAIR, Bn);
    gram_hmma<<<grid, 128, SMEM_DYN>>>(W, bias, out);
}

// round 16
// speedup vs baseline: 1.7180x; 1.7180x over previous
#include <cuda_runtime.h>
#include <cuda_fp16.h>
#include <cstdint>

static constexpr int Bn = 2;
static constexpr int Ln = 2048;
static constexpr int Dn = 1536;
static constexpr int NPAIR = 272;                      // sum_{j<16}(2j+2)
static constexpr int BK = 64;                          // k per stage
static constexpr int NSTG = Dn / BK;                   // 24
static constexpr int NK16 = Dn / 16;                   // 96
static constexpr int A_TILE_B = 64 * BK * 2;           // 8192
static constexpr int B_TILE_B = 128 * BK * 2;          // 16384
static constexpr int STAGE_B = A_TILE_B + B_TILE_B;    // 24576
static constexpr int NSTAGE = 4;
static constexpr int WTAB_OFF = NSTAGE * STAGE_B;      // 98304
static constexpr int WTAB_B = 2 * NK16 * 4 * 2 * 4;    // 6144
static constexpr int SMEM_DYN = WTAB_OFF + WTAB_B;     // 104448 -> 2 CTAs/SM

// single f16 plane per batch: g_h16[b][row][d] = rn16(H)
__device__ __align__(16) __half g_h16[2ull * Ln * Dn];

// ---------------------------------------------------------------- convert (per batch)
__global__ __launch_bounds__(256) void cvt_kernel(const float* __restrict__ H, int b)
{
    const int idx = blockIdx.x * 256 + threadIdx.x;   // Ln*(Dn/4)
    const int d4  = idx % (Dn / 4);
    const int row = idx / (Dn / 4);
    const int d0  = d4 * 4;
    const size_t off = ((size_t)b * Ln + row) * Dn + d0;

    const float4 h = *reinterpret_cast<const float4*>(H + off);
    __half2* q = reinterpret_cast<__half2*>(g_h16 + off);
    q[0] = __floats2half2_rn(h.x, h.y);
    q[1] = __floats2half2_rn(h.z, h.w);
}

// ---------------------------------------------------------------- helpers
__device__ __forceinline__ uint32_t s2u(const void* p) {
    uint32_t a;
    asm("{ .reg .u64 t; cvta.to.shared.u64 t, %1; cvt.u32.u64 %0, t; }" : "=r"(a) : "l"(p));
    return a;
}

// swizzled byte offset inside a (rows x 64 f16) tile (128B rows)
__device__ __forceinline__ uint32_t swz(int row, int c) {
    return (uint32_t)(row * 128 + ((c ^ (row & 7)) << 4));
}

__device__ __forceinline__ uint32_t h2mul(uint32_t a, uint32_t b) {
    __half2 r = __hmul2(*reinterpret_cast<__half2*>(&a), *reinterpret_cast<__half2*>(&b));
    return *reinterpret_cast<uint32_t*>(&r);
}

#define LDSM4(R0, R1, R2, R3, addr)                                            \
    asm volatile("ldmatrix.sync.aligned.m8n8.x4.shared.b16 {%0,%1,%2,%3}, [%4];" \
                 : "=r"(R0), "=r"(R1), "=r"(R2), "=r"(R3) : "r"(addr))

#define MMA(C, A, B)                                                              \
    asm volatile(                                                                 \
        "mma.sync.aligned.m16n8k16.row.col.f32.f16.f16.f32 "                      \
        "{%0,%1,%2,%3},{%4,%5,%6,%7},{%8,%9},{%0,%1,%2,%3};"                      \
        : "+f"((C)[0]), "+f"((C)[1]), "+f"((C)[2]), "+f"((C)[3])                  \
        : "r"((A)[0]), "r"((A)[1]), "r"((A)[2]), "r"((A)[3]),                     \
          "r"((B)[0]), "r"((B)[1]))

// ---------------------------------------------------------------- gram GEMM
// 128 threads = 4 warps in 2(m)x2(n); warp tile 32x64 PER t; CTA tile 64x128
__global__ __launch_bounds__(128, 2)
void gram_hmma(const float* __restrict__ W, const float* __restrict__ bias,
               float* __restrict__ out, int b)
{
    extern __shared__ __align__(1024) char smem_raw[];
    const uint32_t sb = s2u(smem_raw);

    const int tid = threadIdx.x;
    const int wid = tid >> 5;
    const int lane = tid & 31;

    const int wm = (wid >> 1) * 32;   // 0,32
    const int wn = (wid & 1) * 64;    // 0,64

    const int a_row = lane & 15;
    const int ak3   = lane >> 4;
    const int b_row = (lane & 7) + (lane >> 4) * 8;
    const int bk3   = (lane >> 3) & 1;
    const int cquad = lane & 3;

    // decode (row-tile i of 64, col-tile j of 128), i in [0, 2j+1]
    int rem = blockIdx.x, j = 0;
    while (rem >= 2 * j + 2) { rem -= 2 * j + 2; ++j; }
    const int i = rem;
    const int gi0 = i * 64, gj0 = j * 128;
    const bool mirror = (i < 2 * j);

    const __half* srcA = g_h16 + ((size_t)b * Ln + gi0) * Dn;   // 64 rows
    const __half* srcB = g_h16 + ((size_t)b * Ln + gj0) * Dn;   // 128 rows

    auto load_stage = [&](int s, int buf) {
        const int k0 = s * BK;
        const uint32_t sbase = sb + buf * STAGE_B;
        {
            const __half* base = srcA + k0;
#pragma unroll
            for (int q = 0; q < 4; ++q) {
                const int chunk = tid + 128 * q;
                const int row = chunk >> 3, c = chunk & 7;
                asm volatile("cp.async.cg.shared.global [%0], [%1], 16;"
                             :: "r"(sbase + swz(row, c)),
                                "l"(base + (size_t)row * Dn + c * 8) : "memory");
            }
        }
        {
            const __half* base = srcB + k0;
            const uint32_t tb = sbase + A_TILE_B;
#pragma unroll
            for (int q = 0; q < 8; ++q) {
                const int chunk = tid + 128 * q;
                const int row = chunk >> 3, c = chunk & 7;
                asm volatile("cp.async.cg.shared.global [%0], [%1], 16;"
                             :: "r"(tb + swz(row, c)),
                                "l"(base + (size_t)row * Dn + c * 8) : "memory");
            }
        }
        asm volatile("cp.async.commit_group;" ::: "memory");
    };

    load_stage(0, 0);
    load_stage(1, 1);
    load_stage(2, 2);

    // w table: [t][k16][c][e] -> __half2 (w[k], w[k+1]), k = k16*16 + e*8 + c*2
    for (int it = 0; it < 12; ++it) {
        const int idx = tid + 128 * it;          // 0..1535
        const int t = idx / 768;
        const int r = idx % 768;
        const int k16 = r >> 3;
        const int c = (r >> 1) & 3;
        const int e = r & 1;
        const int k = k16 * 16 + e * 8 + c * 2;
        const float* wr = W + (size_t)t * (2 * Dn);
        __half2 v = __floats2half2_rn(wr[k], wr[k + 1]);
        asm volatile("st.shared.u32 [%0], %1;"
                     :: "r"(sb + WTAB_OFF + idx * 4),
                        "r"(*reinterpret_cast<uint32_t*>(&v)) : "memory");
    }

    float acc[2][2][8][4];
#pragma unroll
    for (int t = 0; t < 2; ++t)
#pragma unroll
        for (int mt = 0; mt < 2; ++mt)
#pragma unroll
            for (int nt = 0; nt < 8; ++nt)
#pragma unroll
                for (int e = 0; e < 4; ++e) acc[t][mt][nt][e] = 0.f;

    auto waddr = [&](int t, int k16) {
        return sb + WTAB_OFF + (((t * NK16 + k16) * 4 + cquad) * 2) * 4;
    };

#pragma unroll 1
    for (int s = 0; s < NSTG; ++s) {
        const int buf = s % NSTAGE;
        if (s < NSTG - 2)
            asm volatile("cp.async.wait_group 2;" ::: "memory");
        else if (s == NSTG - 2)
            asm volatile("cp.async.wait_group 1;" ::: "memory");
        else
            asm volatile("cp.async.wait_group 0;" ::: "memory");
        __syncthreads();

        const uint32_t At = sb + buf * STAGE_B;
        const uint32_t Bt = At + A_TILE_B;
        const int k16base = s * 4;

        uint32_t bh[2][8][2], araw[2][4];
        uint32_t w0[2][2], w1[2][2];

        // preamble LDSMs first...
#pragma unroll
        for (int n2 = 0; n2 < 4; ++n2) {
            const int rB = wn + n2 * 16 + b_row;
            LDSM4(bh[0][n2 * 2][0], bh[0][n2 * 2][1],
                  bh[0][n2 * 2 + 1][0], bh[0][n2 * 2 + 1][1], Bt + swz(rB, bk3));
        }
#pragma unroll
        for (int mt = 0; mt < 2; ++mt) {
            const int rA = wm + mt * 16 + a_row;
            LDSM4(araw[mt][0], araw[mt][1], araw[mt][2], araw[mt][3], At + swz(rA, ak3));
        }
        asm volatile("ld.shared.v2.u32 {%0,%1}, [%2];"
                     : "=r"(w0[0][0]), "=r"(w0[0][1]) : "r"(waddr(0, k16base)));
        asm volatile("ld.shared.v2.u32 {%0,%1}, [%2];"
                     : "=r"(w1[0][0]), "=r"(w1[0][1]) : "r"(waddr(1, k16base)));

        // ...then next stage's global load fills the LDSM latency window
        if (s + 3 < NSTG) load_stage(s + 3, (s + 3) % NSTAGE);

#pragma unroll
        for (int s16 = 0; s16 < 4; ++s16) {
            const int cur = s16 & 1;
            if (s16 < 3) {
                const int cbn = (s16 + 1) * 2 + bk3;
#pragma unroll
                for (int n2 = 0; n2 < 4; ++n2) {
                    const int rB = wn + n2 * 16 + b_row;
                    LDSM4(bh[cur ^ 1][n2 * 2][0], bh[cur ^ 1][n2 * 2][1],
                          bh[cur ^ 1][n2 * 2 + 1][0], bh[cur ^ 1][n2 * 2 + 1][1],
                          Bt + swz(rB, cbn));
                }
                asm volatile("ld.shared.v2.u32 {%0,%1}, [%2];"
                             : "=r"(w0[cur ^ 1][0]), "=r"(w0[cur ^ 1][1])
                             : "r"(waddr(0, k16base + s16 + 1)));
                asm volatile("ld.shared.v2.u32 {%0,%1}, [%2];"
                             : "=r"(w1[cur ^ 1][0]), "=r"(w1[cur ^ 1][1])
                             : "r"(waddr(1, k16base + s16 + 1)));
            }

            uint32_t a0[2][4];
#pragma unroll
            for (int mt = 0; mt < 2; ++mt) {
                a0[mt][0] = h2mul(araw[mt][0], w0[cur][0]);
                a0[mt][1] = h2mul(araw[mt][1], w0[cur][0]);
                a0[mt][2] = h2mul(araw[mt][2], w0[cur][1]);
                a0[mt][3] = h2mul(araw[mt][3], w0[cur][1]);
            }
#pragma unroll
            for (int nt = 0; nt < 8; ++nt)
#pragma unroll
                for (int mt = 0; mt < 2; ++mt)
                    MMA(acc[0][mt][nt], a0[mt], bh[cur][nt]);

            uint32_t a1[2][4];
#pragma unroll
            for (int mt = 0; mt < 2; ++mt) {
                a1[mt][0] = h2mul(araw[mt][0], w1[cur][0]);
                a1[mt][1] = h2mul(araw[mt][1], w1[cur][0]);
                a1[mt][2] = h2mul(araw[mt][2], w1[cur][1]);
                a1[mt][3] = h2mul(araw[mt][3], w1[cur][1]);
            }
            if (s16 < 3) {
                const int can = (s16 + 1) * 2 + ak3;
#pragma unroll
                for (int mt = 0; mt < 2; ++mt) {
                    const int rA = wm + mt * 16 + a_row;
                    LDSM4(araw[mt][0], araw[mt][1], araw[mt][2], araw[mt][3],
                          At + swz(rA, can));
                }
            }
#pragma unroll
            for (int nt = 0; nt < 8; ++nt)
#pragma unroll
                for (int mt = 0; mt < 2; ++mt)
                    MMA(acc[1][mt][nt], a1[mt], bh[cur][nt]);
        }
    }

    // ------------------------------------------------------------ epilogue
    const float b0 = __ldg(&bias[0]);
    const float b1 = __ldg(&bias[1]);
    float2* o2 = reinterpret_cast<float2*>(out) + (size_t)b * Ln * Ln;
    const int r4 = lane >> 2;
    const int c4 = (lane & 3) * 2;

#pragma unroll
    for (int mt = 0; mt < 2; ++mt) {
#pragma unroll
        for (int nt = 0; nt < 8; ++nt) {
            const int i0 = gi0 + wm + mt * 16 + r4;
            const int j0 = gj0 + wn + nt * 8 + c4;
            const float2 p00 = make_float2(acc[0][mt][nt][0] + b0, acc[1][mt][nt][0] + b1);
            const float2 p01 = make_float2(acc[0][mt][nt][1] + b0, acc[1][mt][nt][1] + b1);
            const float2 p10 = make_float2(acc[0][mt][nt][2] + b0, acc[1][mt][nt][2] + b1);
            const float2 p11 = make_float2(acc[0][mt][nt][3] + b0, acc[1][mt][nt][3] + b1);
            o2[(size_t)i0 * Ln + j0]           = p00;
            o2[(size_t)i0 * Ln + j0 + 1]       = p01;
            o2[(size_t)(i0 + 8) * Ln + j0]     = p10;
            o2[(size_t)(i0 + 8) * Ln + j0 + 1] = p11;
            if (mirror) {
                o2[(size_t)j0 * Ln + i0]           = p00;
                o2[(size_t)(j0 + 1) * Ln + i0]     = p01;
                o2[(size_t)j0 * Ln + i0 + 8]       = p10;
                o2[(size_t)(j0 + 1) * Ln + i0 + 8] = p11;
            }
        }
    }
}

// ---------------------------------------------------------------- launch
extern "C" void kernel_launch(void* const* d_in, const int* in_sizes, int n_in,
                              void* d_out, int out_size)
{
    const float* H    = (const float*)d_in[0];
    const float* W    = (const float*)d_in[1];
    const float* bias = (const float*)d_in[2];
    float* out = (float*)d_out;

    static bool init_done = false;
    static bool use_streams = false;
    static cudaStream_t s1;
    static cudaEvent_t evF, evJ;
    if (!init_done) {
        cudaFuncSetAttribute(gram_hmma, cudaFuncAttributeMaxDynamicSharedMemorySize,
                             SMEM_DYN);
        use_streams =
            (cudaStreamCreateWithFlags(&s1, cudaStreamNonBlocking) == cudaSuccess) &&
            (cudaEventCreateWithFlags(&evF, cudaEventDisableTiming) == cudaSuccess) &&
            (cudaEventCreateWithFlags(&evJ, cudaEventDisableTiming) == cudaSuccess);
        init_done = true;
    }

    const int cvt_blocks = (Ln * (Dn / 4)) / 256;   // 3072 per batch

    if (use_streams) {
        // fork: cvt_b1 runs on side stream, concurrent with gram_b0
        cvt_kernel<<<cvt_blocks, 256>>>(H, 0);
        cudaEventRecord(evF, 0);
        cudaStreamWaitEvent(s1, evF, 0);
        cvt_kernel<<<cvt_blocks, 256, 0, s1>>>(H, 1);
        gram_hmma<<<NPAIR, 128, SMEM_DYN>>>(W, bias, out, 0);
        cudaEventRecord(evJ, s1);
        cudaStreamWaitEvent(0, evJ, 0);
        gram_hmma<<<NPAIR, 128, SMEM_DYN>>>(W, bias, out, 1);
    } else {
        cvt_kernel<<<cvt_blocks, 256>>>(H, 0);
        cvt_kernel<<<cvt_blocks, 256>>>(H, 1);
        gram_hmma<<<NPAIR, 128, SMEM_DYN>>>(W, bias, out, 0);
        gram_hmma<<<NPAIR, 128, SMEM_DYN>>>(W, bias, out, 1);
    }
}

// round 17
// speedup vs baseline: 1.7878x; 1.0406x over previous
#include <cuda_runtime.h>
#include <cuda_fp16.h>
#include <cstdint>

static constexpr int Bn = 2;
static constexpr int Ln = 2048;
static constexpr int Dn = 1536;
static constexpr int NPAIR = 272;                      // sum_{j<16}(2j+2)
static constexpr int BK = 64;                          // k per stage
static constexpr int NSTG = Dn / BK;                   // 24
static constexpr int NK16 = Dn / 16;                   // 96
static constexpr int A_TILE_B = 64 * BK * 2;           // 8192
static constexpr int B_TILE_B = 128 * BK * 2;          // 16384
static constexpr int STAGE_B = A_TILE_B + B_TILE_B;    // 24576
static constexpr int NSTAGE = 4;
static constexpr int WTAB_OFF = NSTAGE * STAGE_B;      // 98304
static constexpr int WTAB_B = 2 * NK16 * 4 * 2 * 4;    // 6144
static constexpr int SMEM_DYN = WTAB_OFF + WTAB_B;     // 104448 -> 2 CTAs/SM

// single f16 plane per batch: g_h16[b][row][d] = rn16(H)
__device__ __align__(16) __half g_h16[2ull * Ln * Dn];

// ---------------------------------------------------------------- convert (per batch)
__global__ __launch_bounds__(256) void cvt_kernel(const float* __restrict__ H, int b)
{
    const int idx = blockIdx.x * 256 + threadIdx.x;   // Ln*(Dn/4)
    const int d4  = idx % (Dn / 4);
    const int row = idx / (Dn / 4);
    const int d0  = d4 * 4;
    const size_t off = ((size_t)b * Ln + row) * Dn + d0;

    const float4 h = *reinterpret_cast<const float4*>(H + off);
    __half2* q = reinterpret_cast<__half2*>(g_h16 + off);
    q[0] = __floats2half2_rn(h.x, h.y);
    q[1] = __floats2half2_rn(h.z, h.w);
}

// ---------------------------------------------------------------- helpers
__device__ __forceinline__ uint32_t s2u(const void* p) {
    uint32_t a;
    asm("{ .reg .u64 t; cvta.to.shared.u64 t, %1; cvt.u32.u64 %0, t; }" : "=r"(a) : "l"(p));
    return a;
}

// swizzled byte offset inside a (rows x 64 f16) tile (128B rows)
__device__ __forceinline__ uint32_t swz(int row, int c) {
    return (uint32_t)(row * 128 + ((c ^ (row & 7)) << 4));
}

__device__ __forceinline__ uint32_t h2mul(uint32_t a, uint32_t b) {
    __half2 r = __hmul2(*reinterpret_cast<__half2*>(&a), *reinterpret_cast<__half2*>(&b));
    return *reinterpret_cast<uint32_t*>(&r);
}

#define LDSM4(R0, R1, R2, R3, addr)                                            \
    asm volatile("ldmatrix.sync.aligned.m8n8.x4.shared.b16 {%0,%1,%2,%3}, [%4];" \
                 : "=r"(R0), "=r"(R1), "=r"(R2), "=r"(R3) : "r"(addr))

#define MMA(C, A, B)                                                              \
    asm volatile(                                                                 \
        "mma.sync.aligned.m16n8k16.row.col.f32.f16.f16.f32 "                      \
        "{%0,%1,%2,%3},{%4,%5,%6,%7},{%8,%9},{%0,%1,%2,%3};"                      \
        : "+f"((C)[0]), "+f"((C)[1]), "+f"((C)[2]), "+f"((C)[3])                  \
        : "r"((A)[0]), "r"((A)[1]), "r"((A)[2]), "r"((A)[3]),                     \
          "r"((B)[0]), "r"((B)[1]))

// ---------------------------------------------------------------- gram GEMM
// 128 threads = 4 warps in 2(m)x2(n); warp tile 32x64 PER t; CTA tile 64x128
__global__ __launch_bounds__(128, 2)
void gram_hmma(const float* __restrict__ W, const float* __restrict__ bias,
               float* __restrict__ out, int b)
{
    extern __shared__ __align__(1024) char smem_raw[];
    const uint32_t sb = s2u(smem_raw);

    const int tid = threadIdx.x;
    const int wid = tid >> 5;
    const int lane = tid & 31;

    const int wm = (wid >> 1) * 32;   // 0,32
    const int wn = (wid & 1) * 64;    // 0,64

    const int a_row = lane & 15;
    const int ak3   = lane >> 4;
    const int b_row = (lane & 7) + (lane >> 4) * 8;
    const int bk3   = (lane >> 3) & 1;
    const int cquad = lane & 3;

    // decode (row-tile i of 64, col-tile j of 128), i in [0, 2j+1]
    int rem = blockIdx.x, j = 0;
    while (rem >= 2 * j + 2) { rem -= 2 * j + 2; ++j; }
    const int i = rem;
    const int gi0 = i * 64, gj0 = j * 128;
    const bool mirror = (i < 2 * j);

    const __half* srcA = g_h16 + ((size_t)b * Ln + gi0) * Dn;   // 64 rows
    const __half* srcB = g_h16 + ((size_t)b * Ln + gj0) * Dn;   // 128 rows

    auto load_stage = [&](int s, int buf) {
        const int k0 = s * BK;
        const uint32_t sbase = sb + buf * STAGE_B;
        {
            const __half* base = srcA + k0;
#pragma unroll
            for (int q = 0; q < 4; ++q) {
                const int chunk = tid + 128 * q;
                const int row = chunk >> 3, c = chunk & 7;
                asm volatile("cp.async.cg.shared.global [%0], [%1], 16;"
                             :: "r"(sbase + swz(row, c)),
                                "l"(base + (size_t)row * Dn + c * 8) : "memory");
            }
        }
        {
            const __half* base = srcB + k0;
            const uint32_t tb = sbase + A_TILE_B;
#pragma unroll
            for (int q = 0; q < 8; ++q) {
                const int chunk = tid + 128 * q;
                const int row = chunk >> 3, c = chunk & 7;
                asm volatile("cp.async.cg.shared.global [%0], [%1], 16;"
                             :: "r"(tb + swz(row, c)),
                                "l"(base + (size_t)row * Dn + c * 8) : "memory");
            }
        }
        asm volatile("cp.async.commit_group;" ::: "memory");
    };

    load_stage(0, 0);
    load_stage(1, 1);
    load_stage(2, 2);

    // w table: [t][k16][c][e] -> __half2 (w[k], w[k+1]), k = k16*16 + e*8 + c*2
    for (int it = 0; it < 12; ++it) {
        const int idx = tid + 128 * it;          // 0..1535
        const int t = idx / 768;
        const int r = idx % 768;
        const int k16 = r >> 3;
        const int c = (r >> 1) & 3;
        const int e = r & 1;
        const int k = k16 * 16 + e * 8 + c * 2;
        const float* wr = W + (size_t)t * (2 * Dn);
        __half2 v = __floats2half2_rn(wr[k], wr[k + 1]);
        asm volatile("st.shared.u32 [%0], %1;"
                     :: "r"(sb + WTAB_OFF + idx * 4),
                        "r"(*reinterpret_cast<uint32_t*>(&v)) : "memory");
    }

    float acc[2][2][8][4];
#pragma unroll
    for (int t = 0; t < 2; ++t)
#pragma unroll
        for (int mt = 0; mt < 2; ++mt)
#pragma unroll
            for (int nt = 0; nt < 8; ++nt)
#pragma unroll
                for (int e = 0; e < 4; ++e) acc[t][mt][nt][e] = 0.f;

    auto waddr = [&](int t, int k16) {
        return sb + WTAB_OFF + (((t * NK16 + k16) * 4 + cquad) * 2) * 4;
    };

#pragma unroll 1
    for (int s = 0; s < NSTG; ++s) {
        const int buf = s % NSTAGE;
        if (s < NSTG - 2)
            asm volatile("cp.async.wait_group 2;" ::: "memory");
        else if (s == NSTG - 2)
            asm volatile("cp.async.wait_group 1;" ::: "memory");
        else
            asm volatile("cp.async.wait_group 0;" ::: "memory");
        __syncthreads();

        const uint32_t At = sb + buf * STAGE_B;
        const uint32_t Bt = At + A_TILE_B;
        const int k16base = s * 4;

        uint32_t bh[2][8][2], araw[2][4];
        uint32_t w0[2][2], w1[2][2];

        // preamble LDSMs first...
#pragma unroll
        for (int n2 = 0; n2 < 4; ++n2) {
            const int rB = wn + n2 * 16 + b_row;
            LDSM4(bh[0][n2 * 2][0], bh[0][n2 * 2][1],
                  bh[0][n2 * 2 + 1][0], bh[0][n2 * 2 + 1][1], Bt + swz(rB, bk3));
        }
#pragma unroll
        for (int mt = 0; mt < 2; ++mt) {
            const int rA = wm + mt * 16 + a_row;
            LDSM4(araw[mt][0], araw[mt][1], araw[mt][2], araw[mt][3], At + swz(rA, ak3));
        }
        asm volatile("ld.shared.v2.u32 {%0,%1}, [%2];"
                     : "=r"(w0[0][0]), "=r"(w0[0][1]) : "r"(waddr(0, k16base)));
        asm volatile("ld.shared.v2.u32 {%0,%1}, [%2];"
                     : "=r"(w1[0][0]), "=r"(w1[0][1]) : "r"(waddr(1, k16base)));

        // ...then next stage's global load fills the LDSM latency window
        if (s + 3 < NSTG) load_stage(s + 3, (s + 3) % NSTAGE);

#pragma unroll
        for (int s16 = 0; s16 < 4; ++s16) {
            const int cur = s16 & 1;
            if (s16 < 3) {
                const int cbn = (s16 + 1) * 2 + bk3;
#pragma unroll
                for (int n2 = 0; n2 < 4; ++n2) {
                    const int rB = wn + n2 * 16 + b_row;
                    LDSM4(bh[cur ^ 1][n2 * 2][0], bh[cur ^ 1][n2 * 2][1],
                          bh[cur ^ 1][n2 * 2 + 1][0], bh[cur ^ 1][n2 * 2 + 1][1],
                          Bt + swz(rB, cbn));
                }
                asm volatile("ld.shared.v2.u32 {%0,%1}, [%2];"
                             : "=r"(w0[cur ^ 1][0]), "=r"(w0[cur ^ 1][1])
                             : "r"(waddr(0, k16base + s16 + 1)));
                asm volatile("ld.shared.v2.u32 {%0,%1}, [%2];"
                             : "=r"(w1[cur ^ 1][0]), "=r"(w1[cur ^ 1][1])
                             : "r"(waddr(1, k16base + s16 + 1)));
            }

            uint32_t a0[2][4];
#pragma unroll
            for (int mt = 0; mt < 2; ++mt) {
                a0[mt][0] = h2mul(araw[mt][0], w0[cur][0]);
                a0[mt][1] = h2mul(araw[mt][1], w0[cur][0]);
                a0[mt][2] = h2mul(araw[mt][2], w0[cur][1]);
                a0[mt][3] = h2mul(araw[mt][3], w0[cur][1]);
            }
#pragma unroll
            for (int nt = 0; nt < 8; ++nt)
#pragma unroll
                for (int mt = 0; mt < 2; ++mt)
                    MMA(acc[0][mt][nt], a0[mt], bh[cur][nt]);

            uint32_t a1[2][4];
#pragma unroll
            for (int mt = 0; mt < 2; ++mt) {
                a1[mt][0] = h2mul(araw[mt][0], w1[cur][0]);
                a1[mt][1] = h2mul(araw[mt][1], w1[cur][0]);
                a1[mt][2] = h2mul(araw[mt][2], w1[cur][1]);
                a1[mt][3] = h2mul(araw[mt][3], w1[cur][1]);
            }
            if (s16 < 3) {
                const int can = (s16 + 1) * 2 + ak3;
#pragma unroll
                for (int mt = 0; mt < 2; ++mt) {
                    const int rA = wm + mt * 16 + a_row;
                    LDSM4(araw[mt][0], araw[mt][1], araw[mt][2], araw[mt][3],
                          At + swz(rA, can));
                }
            }
#pragma unroll
            for (int nt = 0; nt < 8; ++nt)
#pragma unroll
                for (int mt = 0; mt < 2; ++mt)
                    MMA(acc[1][mt][nt], a1[mt], bh[cur][nt]);
        }
    }

    // ------------------------------------------------------------ epilogue
    const float b0 = __ldg(&bias[0]);
    const float b1 = __ldg(&bias[1]);
    float2* o2 = reinterpret_cast<float2*>(out) + (size_t)b * Ln * Ln;
    const int r4 = lane >> 2;
    const int c4 = (lane & 3) * 2;

#pragma unroll
    for (int mt = 0; mt < 2; ++mt) {
#pragma unroll
        for (int nt = 0; nt < 8; ++nt) {
            const int i0 = gi0 + wm + mt * 16 + r4;
            const int j0 = gj0 + wn + nt * 8 + c4;
            const float2 p00 = make_float2(acc[0][mt][nt][0] + b0, acc[1][mt][nt][0] + b1);
            const float2 p01 = make_float2(acc[0][mt][nt][1] + b0, acc[1][mt][nt][1] + b1);
            const float2 p10 = make_float2(acc[0][mt][nt][2] + b0, acc[1][mt][nt][2] + b1);
            const float2 p11 = make_float2(acc[0][mt][nt][3] + b0, acc[1][mt][nt][3] + b1);
            o2[(size_t)i0 * Ln + j0]           = p00;
            o2[(size_t)i0 * Ln + j0 + 1]       = p01;
            o2[(size_t)(i0 + 8) * Ln + j0]     = p10;
            o2[(size_t)(i0 + 8) * Ln + j0 + 1] = p11;
            if (mirror) {
                o2[(size_t)j0 * Ln + i0]           = p00;
                o2[(size_t)(j0 + 1) * Ln + i0]     = p01;
                o2[(size_t)j0 * Ln + i0 + 8]       = p10;
                o2[(size_t)(j0 + 1) * Ln + i0 + 8] = p11;
            }
        }
    }
}

// ---------------------------------------------------------------- launch
extern "C" void kernel_launch(void* const* d_in, const int* in_sizes, int n_in,
                              void* d_out, int out_size)
{
    const float* H    = (const float*)d_in[0];
    const float* W    = (const float*)d_in[1];
    const float* bias = (const float*)d_in[2];
    float* out = (float*)d_out;

    static bool init_done = false;
    static bool use_streams = false;
    static cudaStream_t s1;
    static cudaEvent_t evF, evJ;
    if (!init_done) {
        cudaFuncSetAttribute(gram_hmma, cudaFuncAttributeMaxDynamicSharedMemorySize,
                             SMEM_DYN);
        use_streams =
            (cudaStreamCreateWithFlags(&s1, cudaStreamNonBlocking) == cudaSuccess) &&
            (cudaEventCreateWithFlags(&evF, cudaEventDisableTiming) == cudaSuccess) &&
            (cudaEventCreateWithFlags(&evJ, cudaEventDisableTiming) == cudaSuccess);
        init_done = true;
    }

    const int cvt_blocks = (Ln * (Dn / 4)) / 256;   // 3072 per batch

    if (use_streams) {
        // default: cvt_b0 -> gram_b0
        // s1:      (after cvt_b0) cvt_b1 -> gram_b1   (concurrent with gram_b0)
        cvt_kernel<<<cvt_blocks, 256>>>(H, 0);
        cudaEventRecord(evF, 0);
        cudaStreamWaitEvent(s1, evF, 0);
        cvt_kernel<<<cvt_blocks, 256, 0, s1>>>(H, 1);
        gram_hmma<<<NPAIR, 128, SMEM_DYN>>>(W, bias, out, 0);
        gram_hmma<<<NPAIR, 128, SMEM_DYN, s1>>>(W, bias, out, 1);
        cudaEventRecord(evJ, s1);
        cudaStreamWaitEvent(0, evJ, 0);
    } else {
        cvt_kernel<<<cvt_blocks, 256>>>(H, 0);
        cvt_kernel<<<cvt_blocks, 256>>>(H, 1);
        gram_hmma<<<NPAIR, 128, SMEM_DYN>>>(W, bias, out, 0);
        gram_hmma<<<NPAIR, 128, SMEM_DYN>>>(W, bias, out, 1);
    }
}